// round 10
// baseline (speedup 1.0000x reference)
#include <cuda_runtime.h>
#include <cuda_fp16.h>
#include <cstdint>

// ---------------------------------------------------------------------------
// DialogueTransformer on GB300 (sm_103a, base sm_103 PTX => legacy mma.sync).
// R10: single-product fp16 HMMA GEMMs; ONE mega weight-convert into a
// contiguous fp16 arena (no converts between dependent GEMMs); attn handles
// 2 positions per 256-thread block; two-stream fork/join retained.
// ---------------------------------------------------------------------------

#define MDIM 16384
#define DDIM 1024

// fp16 activation buffers
__device__ __align__(256) __half g_q1[MDIM * 3 * DDIM];   // enc QKV
__device__ __align__(256) __half g_q2[MDIM * 3 * DDIM];   // dec-self QKV
__device__ __align__(256) __half g_kvb[MDIM * 2 * DDIM];  // cross K,V
__device__ __align__(256) __half g_cq[MDIM * DDIM];       // cross Q
__device__ __align__(256) __half g_xq[MDIM * DDIM];       // enc input
__device__ __align__(256) __half g_yq[MDIM * DDIM];       // dec input
__device__ __align__(256) __half g_aq[MDIM * DDIM];       // enc attn out
__device__ __align__(256) __half g_sa[MDIM * DDIM];       // dec self-attn out
__device__ __align__(256) __half g_pq[MDIM * DDIM];       // ffn hidden
__device__ __align__(256) __half g_eq[MDIM * DDIM];       // enc_out
__device__ __align__(256) __half g_ca[MDIM * DDIM];       // cross attn out
// single fp16 weight arena: 14 slots of 1M halves
// slots: 0-2 enc qkv | 3 enc w1 | 4 enc w2 | 5-7 dec_s qkv | 8 dec_c q
//        9-10 dec_c k,v | 11 dec w1 | 12 dec w2 | 13 fc
__device__ __align__(256) __half g_wall[14u << 20];

// ---------------------------------------------------------------------------
// PTX helpers (baseline sm_80+ PTX only)
// ---------------------------------------------------------------------------
__device__ __forceinline__ uint32_t smem_to_u32(const void* p) {
    uint32_t a;
    asm("{ .reg .u64 t; cvta.to.shared.u64 t, %1; cvt.u32.u64 %0, t; }" : "=r"(a) : "l"(p));
    return a;
}
__device__ __forceinline__ void cp_async16(uint32_t saddr, const void* gptr) {
    asm volatile("cp.async.cg.shared.global [%0], [%1], 16;" :: "r"(saddr), "l"(gptr));
}
__device__ __forceinline__ void cp_commit() { asm volatile("cp.async.commit_group;"); }
__device__ __forceinline__ void cp_wait_all() { asm volatile("cp.async.wait_group 0;" ::: "memory"); }

__device__ __forceinline__ void ldsm_x4(uint32_t* r, uint32_t addr) {
    asm volatile("ldmatrix.sync.aligned.m8n8.x4.shared.b16 {%0,%1,%2,%3}, [%4];"
                 : "=r"(r[0]), "=r"(r[1]), "=r"(r[2]), "=r"(r[3]) : "r"(addr));
}
__device__ __forceinline__ void mma16816(float* c, const uint32_t* a,
                                         uint32_t b0, uint32_t b1) {
    asm volatile(
        "mma.sync.aligned.m16n8k16.row.col.f32.f16.f16.f32 "
        "{%0,%1,%2,%3}, {%4,%5,%6,%7}, {%8,%9}, {%0,%1,%2,%3};"
        : "+f"(c[0]), "+f"(c[1]), "+f"(c[2]), "+f"(c[3])
        : "r"(a[0]), "r"(a[1]), "r"(a[2]), "r"(a[3]), "r"(b0), "r"(b1));
}

// ---------------------------------------------------------------------------
// fp16 GEMM: C[m,gn] = sum_k a[m,k]*w[gn,k] + bias(gn)
// BM=128, BN=128, BK=32 halves, 256 thr, 8 warps (2x4 -> 64x32 warp tiles).
// ---------------------------------------------------------------------------
#define BM 128
#define BN 128
#define BK 32
#define NKB (DDIM / BK)   // 32
#define ROWB 80
#define TILE_BYTES (128 * ROWB)          // 10240
#define STAGE_BYTES (2 * TILE_BYTES)     // A, W = 20480
#define GEMM_SMEM (2 * STAGE_BYTES)      // 40960

template <bool RELU, bool F16OUT>
__global__ __launch_bounds__(256, 2)
void gemm_f16(const __half* __restrict__ Ag,
              const __half* __restrict__ Wg,
              const float* __restrict__ b0, const float* __restrict__ b1,
              const float* __restrict__ b2,
              float* __restrict__ Cf, __half* __restrict__ Ch, int ldc) {
    extern __shared__ char smem[];
    const uint32_t sb = smem_to_u32(smem);
    const int tid = threadIdx.x;
    const int wid = tid >> 5;
    const int lane = tid & 31;
    const int bm = blockIdx.y * BM;
    const int gn = blockIdx.x * BN;
    const int wm = (wid & 1) * 64;
    const int wn = (wid >> 1) * 32;

    auto OFF_A = [](int s) { return s * STAGE_BYTES + 0 * TILE_BYTES; };
    auto OFF_W = [](int s) { return s * STAGE_BYTES + 1 * TILE_BYTES; };

    const int fr = tid >> 1;
    const int fc0 = (tid & 1) * 2;
    const __half* gA = Ag + (size_t)(bm + fr) * DDIM;
    const __half* gW = Wg + (size_t)(gn + fr) * DDIM;

    auto fill_stage = [&](int s, int kb) {
        const int k0 = kb * BK;
        const uint32_t srow = fr * ROWB;
#pragma unroll
        for (int i = 0; i < 2; i++) {
            const int c = fc0 + i;
            const uint32_t so = srow + c * 16;
            const int go = k0 + c * 8;
            cp_async16(sb + OFF_A(s) + so, gA + go);
            cp_async16(sb + OFF_W(s) + so, gW + go);
        }
        cp_commit();
    };

    fill_stage(0, 0);
    cp_wait_all();
    __syncthreads();

    float acc[4][4][4];
#pragma unroll
    for (int i = 0; i < 4; i++)
#pragma unroll
        for (int j = 0; j < 4; j++)
#pragma unroll
            for (int q = 0; q < 4; q++) acc[i][j][q] = 0.0f;

    const uint32_t lrow = (lane & 15);
    const uint32_t lcol = (lane >> 4) * 16;

    for (int kb = 0; kb < NKB; kb++) {
        const int s = kb & 1;
        if (kb + 1 < NKB) fill_stage(s ^ 1, kb + 1);

        const uint32_t ab = sb + OFF_A(s) + (wm + lrow) * ROWB + lcol;
        const uint32_t wb = sb + OFF_W(s) + (wn + lrow) * ROWB + lcol;

#pragma unroll
        for (int ks = 0; ks < 2; ks++) {
            const uint32_t ko = ks * 32;
            uint32_t bf[2][4];
#pragma unroll
            for (int p = 0; p < 2; p++)
                ldsm_x4(bf[p], wb + p * (16 * ROWB) + ko);
#pragma unroll
            for (int mt = 0; mt < 4; mt++) {
                uint32_t af[4];
                ldsm_x4(af, ab + mt * (16 * ROWB) + ko);
#pragma unroll
                for (int nt = 0; nt < 4; nt++) {
                    const int p = nt >> 1, o = nt & 1;
                    mma16816(acc[mt][nt], af, bf[p][o], bf[p][o + 2]);
                }
            }
        }
        if (kb + 1 < NKB) cp_wait_all();
        __syncthreads();
    }

    // ---- epilogue ----
    const int g = lane >> 2, t4 = lane & 3;
    const float* bias = (blockIdx.x < 8) ? b0 : ((blockIdx.x < 16) ? b1 : b2);
    const int bb = (blockIdx.x & 7) * BN + wn;

#pragma unroll
    for (int mt = 0; mt < 4; mt++) {
        const int row0 = bm + wm + mt * 16 + g;
#pragma unroll
        for (int nt = 0; nt < 4; nt++) {
            const int col = nt * 8 + 2 * t4;
            const float bx = bias[bb + col];
            const float by = bias[bb + col + 1];
            float2 v0, v1;
            v0.x = acc[mt][nt][0] + bx;
            v0.y = acc[mt][nt][1] + by;
            v1.x = acc[mt][nt][2] + bx;
            v1.y = acc[mt][nt][3] + by;
            if (RELU) {
                v0.x = fmaxf(v0.x, 0.0f); v0.y = fmaxf(v0.y, 0.0f);
                v1.x = fmaxf(v1.x, 0.0f); v1.y = fmaxf(v1.y, 0.0f);
            }
            const size_t o0 = (size_t)row0 * ldc + gn + wn + col;
            if (F16OUT) {
                *(__half2*)(Ch + o0) = __floats2half2_rn(v0.x, v0.y);
                *(__half2*)(Ch + o0 + 8 * (size_t)ldc) = __floats2half2_rn(v1.x, v1.y);
            } else {
                *(float2*)(Cf + o0) = v0;
                *(float2*)(Cf + o0 + 8 * (size_t)ldc) = v1;
            }
        }
    }
}

// ---------------------------------------------------------------------------
// Converters
// ---------------------------------------------------------------------------
template <bool PE>
__global__ __launch_bounds__(256)
void conv_act(const float* __restrict__ x, const float* __restrict__ pe,
              __half* __restrict__ out) {
    const size_t i = ((size_t)blockIdx.x * 256 + threadIdx.x) * 4;
    float4 v = *(const float4*)(x + i);
    if (PE) {
        const int d = (int)(i & (DDIM - 1));
        v.x += pe[d + 0]; v.y += pe[d + 1]; v.z += pe[d + 2]; v.w += pe[d + 3];
    }
    __half2 h01 = __floats2half2_rn(v.x, v.y);
    __half2 h23 = __floats2half2_rn(v.z, v.w);
    *(uint2*)(out + i) = make_uint2(*(uint32_t*)&h01, *(uint32_t*)&h23);
}

// all 14 weight matrices -> fp16 arena in one launch
struct WPtrs { const float* p[14]; };

__global__ __launch_bounds__(256)
void conv_w_all(WPtrs w, __half* __restrict__ dst) {
    const size_t i = ((size_t)blockIdx.x * 256 + threadIdx.x) * 4;
    const int mat = (int)(i >> 20);
    const uint32_t off = (uint32_t)(i & ((1u << 20) - 1));
    float4 v = *(const float4*)(w.p[mat] + off);
    __half2 h01 = __floats2half2_rn(v.x, v.y);
    __half2 h23 = __floats2half2_rn(v.z, v.w);
    *(uint2*)(dst + i) = make_uint2(*(uint32_t*)&h01, *(uint32_t*)&h23);
}

// ---------------------------------------------------------------------------
// Per-position 8x8 head-mix attention; 2 positions per 256-thread block.
// fp16 strided inputs, fp16 output.
// ---------------------------------------------------------------------------
#define QROW 132

__global__ __launch_bounds__(256)
void attn_kernel(const __half* __restrict__ Q, int qs,
                 const __half* __restrict__ K, int ks_,
                 const __half* __restrict__ V, int vs,
                 __half* __restrict__ O) {
    __shared__ float sq[2][8 * QROW + 4];
    __shared__ float sk[2][8 * QROW + 4];
    __shared__ float sw[2][64];

    const int hid = threadIdx.x >> 7;        // position half: 0/1
    const int t = threadIdx.x & 127;
    const int p = blockIdx.x * 2 + hid;
    const __half* Qb = Q + (size_t)p * qs;
    const __half* Kb = K + (size_t)p * ks_;
    const __half* Vb = V + (size_t)p * vs;
    float* mq = sq[hid];
    float* mk = sk[hid];
    float* mw = sw[hid];

    // load 1024 halves of q and k each (8 per thread), convert to fp32 smem
    {
        const int e = t * 8;
        const int i = e >> 7, h = e & 127;
        uint4 rq = *(const uint4*)(Qb + e);
        uint4 rk = *(const uint4*)(Kb + e);
        const __half2* qp = (const __half2*)&rq;
        const __half2* kp = (const __half2*)&rk;
        float* dq = mq + i * QROW + h;
        float* dk = mk + i * QROW + h;
#pragma unroll
        for (int w = 0; w < 4; w++) {
            const float2 fq = __half22float2(qp[w]);
            const float2 fk = __half22float2(kp[w]);
            dq[2 * w] = fq.x; dq[2 * w + 1] = fq.y;
            dk[2 * w] = fk.x; dk[2 * w + 1] = fk.y;
        }
    }
    __syncthreads();

    // scores: 128 threads per position; 2 threads per (i,j), each half of h
    {
        const int pair = t >> 1;              // 0..63
        const int sub = t & 1;                // which h-half
        const int i = pair >> 3, j = pair & 7;
        const float* qi = &mq[i * QROW + sub * 64];
        const float* kj = &mk[j * QROW + sub * 64];
        float s = 0.0f;
#pragma unroll
        for (int h = 0; h < 64; h += 4) {
            const float4 a = *(const float4*)(qi + h);
            const float4 b = *(const float4*)(kj + h);
            s += a.x * b.x + a.y * b.y + a.z * b.z + a.w * b.w;
        }
        s += __shfl_xor_sync(0xffffffffu, s, 1);
        if (sub == 0) mw[pair] = s * 0.08838834764831845f;
    }
    __syncthreads();

    if (t < 8) {
        float m = mw[t * 8];
#pragma unroll
        for (int j = 1; j < 8; j++) m = fmaxf(m, mw[t * 8 + j]);
        float s = 0.0f;
        float e[8];
#pragma unroll
        for (int j = 0; j < 8; j++) { e[j] = __expf(mw[t * 8 + j] - m); s += e[j]; }
        const float inv = 1.0f / s;
#pragma unroll
        for (int j = 0; j < 8; j++) mw[t * 8 + j] = e[j] * inv;
    }
    __syncthreads();

    float vj[8];
#pragma unroll
    for (int j = 0; j < 8; j++) vj[j] = __half2float(Vb[j * 128 + t]);
    const size_t obase = (size_t)p * 1024;
#pragma unroll
    for (int i = 0; i < 8; i++) {
        float o = 0.0f;
#pragma unroll
        for (int j = 0; j < 8; j++) o += mw[i * 8 + j] * vj[j];
        O[obase + i * 128 + t] = __float2half_rn(o);
    }
}

// ---------------------------------------------------------------------------
// Launch — two streams: s0 = default (encoder + tail), s1 = decoder-self.
// ---------------------------------------------------------------------------
extern "C" void kernel_launch(void* const* d_in, const int* in_sizes, int n_in,
                              void* d_out, int out_size) {
    const float* input_seq  = (const float*)d_in[0];
    const float* output_seq = (const float*)d_in[1];
    const float* pe         = (const float*)d_in[2];

    WPtrs wp;
    // slots: 0-2 enc qkv | 3 enc w1 | 4 enc w2 | 5-7 dec_s qkv | 8 dec_c q
    //        9-10 dec_c k,v | 11 dec w1 | 12 dec w2 | 13 fc
    wp.p[0]  = (const float*)d_in[3];   // enc_wq
    wp.p[1]  = (const float*)d_in[5];   // enc_wk
    wp.p[2]  = (const float*)d_in[7];   // enc_wv
    wp.p[3]  = (const float*)d_in[9];   // enc_w1
    wp.p[4]  = (const float*)d_in[11];  // enc_w2
    wp.p[5]  = (const float*)d_in[13];  // dec_s_wq
    wp.p[6]  = (const float*)d_in[15];  // dec_s_wk
    wp.p[7]  = (const float*)d_in[17];  // dec_s_wv
    wp.p[8]  = (const float*)d_in[19];  // dec_c_wq
    wp.p[9]  = (const float*)d_in[21];  // dec_c_wk
    wp.p[10] = (const float*)d_in[23];  // dec_c_wv
    wp.p[11] = (const float*)d_in[25];  // dec_w1
    wp.p[12] = (const float*)d_in[27];  // dec_w2
    wp.p[13] = (const float*)d_in[29];  // fc_w
    const float* enc_bq = (const float*)d_in[4];
    const float* enc_bk = (const float*)d_in[6];
    const float* enc_bv = (const float*)d_in[8];
    const float* enc_b1 = (const float*)d_in[10];
    const float* enc_b2 = (const float*)d_in[12];
    const float* dec_s_bq = (const float*)d_in[14];
    const float* dec_s_bk = (const float*)d_in[16];
    const float* dec_s_bv = (const float*)d_in[18];
    const float* dec_c_bq = (const float*)d_in[20];
    const float* dec_c_bk = (const float*)d_in[22];
    const float* dec_c_bv = (const float*)d_in[24];
    const float* dec_b1 = (const float*)d_in[26];
    const float* dec_b2 = (const float*)d_in[28];
    const float* fc_b   = (const float*)d_in[30];

    __half *Q1, *Q2, *KVb, *Cq, *Xq, *Yq, *Aq, *Sa, *Pq, *Eq, *Ca, *WALL;
    cudaGetSymbolAddress((void**)&Q1, g_q1);
    cudaGetSymbolAddress((void**)&Q2, g_q2);
    cudaGetSymbolAddress((void**)&KVb, g_kvb);
    cudaGetSymbolAddress((void**)&Cq, g_cq);
    cudaGetSymbolAddress((void**)&Xq, g_xq);
    cudaGetSymbolAddress((void**)&Yq, g_yq);
    cudaGetSymbolAddress((void**)&Aq, g_aq);
    cudaGetSymbolAddress((void**)&Sa, g_sa);
    cudaGetSymbolAddress((void**)&Pq, g_pq);
    cudaGetSymbolAddress((void**)&Eq, g_eq);
    cudaGetSymbolAddress((void**)&Ca, g_ca);
    cudaGetSymbolAddress((void**)&WALL, g_wall);
    float* OUT = (float*)d_out;
    auto WSLOT = [&](int s) { return WALL + ((size_t)s << 20); };

    cudaFuncSetAttribute(gemm_f16<false,false>, cudaFuncAttributeMaxDynamicSharedMemorySize, GEMM_SMEM);
    cudaFuncSetAttribute(gemm_f16<false,true>,  cudaFuncAttributeMaxDynamicSharedMemorySize, GEMM_SMEM);
    cudaFuncSetAttribute(gemm_f16<true,true>,   cudaFuncAttributeMaxDynamicSharedMemorySize, GEMM_SMEM);

    static cudaStream_t s1 = nullptr;
    static cudaEvent_t evFork = nullptr, evJoin = nullptr;
    if (!s1) {
        cudaStreamCreateWithFlags(&s1, cudaStreamNonBlocking);
        cudaEventCreateWithFlags(&evFork, cudaEventDisableTiming);
        cudaEventCreateWithFlags(&evJoin, cudaEventDisableTiming);
    }

    const int CA_BLK = MDIM * DDIM / (4 * 256);   // 16384

    auto gemmH16 = [&](cudaStream_t st, int ng, const __half* a, const __half* w,
                       const float* bb0, const float* bb1, const float* bb2,
                       __half* C, int ldc, bool relu) {
        if (relu)
            gemm_f16<true,true><<<dim3(ng * 8, MDIM / BM), 256, GEMM_SMEM, st>>>(
                a, w, bb0, bb1, bb2, nullptr, C, ldc);
        else
            gemm_f16<false,true><<<dim3(ng * 8, MDIM / BM), 256, GEMM_SMEM, st>>>(
                a, w, bb0, bb1, bb2, nullptr, C, ldc);
    };

    // ---- all weights converted once, before the fork ----
    conv_w_all<<<14 * 1024, 256>>>(wp, WALL);

    // ---- fork ----
    cudaEventRecord(evFork, 0);
    cudaStreamWaitEvent(s1, evFork, 0);

    // ========== stream s1: decoder-self branch through cross-Q ==========
    conv_act<false><<<CA_BLK, 256, 0, s1>>>(output_seq, nullptr, Yq);
    gemmH16(s1, 3, Yq, WSLOT(5), dec_s_bq, dec_s_bk, dec_s_bv, Q2, 3 * DDIM, false);
    attn_kernel<<<MDIM / 2, 256, 0, s1>>>(Q2, 3 * DDIM, Q2 + DDIM, 3 * DDIM,
                                          Q2 + 2 * DDIM, 3 * DDIM, Sa);
    gemmH16(s1, 1, Sa, WSLOT(8), dec_c_bq, dec_c_bq, dec_c_bq, Cq, DDIM, false);
    cudaEventRecord(evJoin, s1);

    // ========== stream 0: encoder branch ==========
    conv_act<true><<<CA_BLK, 256>>>(input_seq, pe, Xq);
    gemmH16(0, 3, Xq, WSLOT(0), enc_bq, enc_bk, enc_bv, Q1, 3 * DDIM, false);
    attn_kernel<<<MDIM / 2, 256>>>(Q1, 3 * DDIM, Q1 + DDIM, 3 * DDIM,
                                   Q1 + 2 * DDIM, 3 * DDIM, Aq);
    gemmH16(0, 1, Aq, WSLOT(3), enc_b1, enc_b1, enc_b1, Pq, DDIM, true);
    gemmH16(0, 1, Pq, WSLOT(4), enc_b2, enc_b2, enc_b2, Eq, DDIM, false);
    gemmH16(0, 2, Eq, WSLOT(9), dec_c_bk, dec_c_bv, dec_c_bv, KVb, 2 * DDIM, false);

    // ---- join ----
    cudaStreamWaitEvent(0, evJoin, 0);

    // ========== stream 0: cross-attn + decoder FFN + fc ==========
    attn_kernel<<<MDIM / 2, 256>>>(Cq, DDIM, KVb, 2 * DDIM, KVb + DDIM, 2 * DDIM, Ca);
    gemmH16(0, 1, Ca, WSLOT(11), dec_b1, dec_b1, dec_b1, Pq, DDIM, true);
    gemmH16(0, 1, Pq, WSLOT(12), dec_b2, dec_b2, dec_b2, Xq, DDIM, false);
    gemm_f16<false,false><<<dim3(8, MDIM / BM), 256, GEMM_SMEM>>>(
        Xq, WSLOT(13), fc_b, fc_b, fc_b, OUT, nullptr, DDIM);
}

// round 11
// speedup vs baseline: 1.0237x; 1.0237x over previous
#include <cuda_runtime.h>
#include <cuda_fp16.h>
#include <cstdint>

// ---------------------------------------------------------------------------
// DialogueTransformer on GB300 (sm_103a, base sm_103 PTX => legacy mma.sync).
// R11: R9's proven attn kernel (1 pos / 128 thr) + R10's single mega
// weight-convert arena + two-stream fork/join. GEMM engine unchanged
// (single-product fp16 HMMA at the legacy-pipe issue floor).
// ---------------------------------------------------------------------------

#define MDIM 16384
#define DDIM 1024

// fp16 activation buffers
__device__ __align__(256) __half g_q1[MDIM * 3 * DDIM];   // enc QKV
__device__ __align__(256) __half g_q2[MDIM * 3 * DDIM];   // dec-self QKV
__device__ __align__(256) __half g_kvb[MDIM * 2 * DDIM];  // cross K,V
__device__ __align__(256) __half g_cq[MDIM * DDIM];       // cross Q
__device__ __align__(256) __half g_xq[MDIM * DDIM];       // enc input
__device__ __align__(256) __half g_yq[MDIM * DDIM];       // dec input
__device__ __align__(256) __half g_aq[MDIM * DDIM];       // enc attn out
__device__ __align__(256) __half g_sa[MDIM * DDIM];       // dec self-attn out
__device__ __align__(256) __half g_pq[MDIM * DDIM];       // ffn hidden
__device__ __align__(256) __half g_eq[MDIM * DDIM];       // enc_out
__device__ __align__(256) __half g_ca[MDIM * DDIM];       // cross attn out
// single fp16 weight arena: 14 slots of 1M halves
// slots: 0-2 enc qkv | 3 enc w1 | 4 enc w2 | 5-7 dec_s qkv | 8 dec_c q
//        9-10 dec_c k,v | 11 dec w1 | 12 dec w2 | 13 fc
__device__ __align__(256) __half g_wall[14u << 20];

// ---------------------------------------------------------------------------
// PTX helpers (baseline sm_80+ PTX only)
// ---------------------------------------------------------------------------
__device__ __forceinline__ uint32_t smem_to_u32(const void* p) {
    uint32_t a;
    asm("{ .reg .u64 t; cvta.to.shared.u64 t, %1; cvt.u32.u64 %0, t; }" : "=r"(a) : "l"(p));
    return a;
}
__device__ __forceinline__ void cp_async16(uint32_t saddr, const void* gptr) {
    asm volatile("cp.async.cg.shared.global [%0], [%1], 16;" :: "r"(saddr), "l"(gptr));
}
__device__ __forceinline__ void cp_commit() { asm volatile("cp.async.commit_group;"); }
__device__ __forceinline__ void cp_wait_all() { asm volatile("cp.async.wait_group 0;" ::: "memory"); }

__device__ __forceinline__ void ldsm_x4(uint32_t* r, uint32_t addr) {
    asm volatile("ldmatrix.sync.aligned.m8n8.x4.shared.b16 {%0,%1,%2,%3}, [%4];"
                 : "=r"(r[0]), "=r"(r[1]), "=r"(r[2]), "=r"(r[3]) : "r"(addr));
}
__device__ __forceinline__ void mma16816(float* c, const uint32_t* a,
                                         uint32_t b0, uint32_t b1) {
    asm volatile(
        "mma.sync.aligned.m16n8k16.row.col.f32.f16.f16.f32 "
        "{%0,%1,%2,%3}, {%4,%5,%6,%7}, {%8,%9}, {%0,%1,%2,%3};"
        : "+f"(c[0]), "+f"(c[1]), "+f"(c[2]), "+f"(c[3])
        : "r"(a[0]), "r"(a[1]), "r"(a[2]), "r"(a[3]), "r"(b0), "r"(b1));
}

// ---------------------------------------------------------------------------
// fp16 GEMM: C[m,gn] = sum_k a[m,k]*w[gn,k] + bias(gn)
// BM=128, BN=128, BK=32 halves, 256 thr, 8 warps (2x4 -> 64x32 warp tiles).
// ---------------------------------------------------------------------------
#define BM 128
#define BN 128
#define BK 32
#define NKB (DDIM / BK)   // 32
#define ROWB 80
#define TILE_BYTES (128 * ROWB)          // 10240
#define STAGE_BYTES (2 * TILE_BYTES)     // A, W = 20480
#define GEMM_SMEM (2 * STAGE_BYTES)      // 40960

template <bool RELU, bool F16OUT>
__global__ __launch_bounds__(256, 2)
void gemm_f16(const __half* __restrict__ Ag,
              const __half* __restrict__ Wg,
              const float* __restrict__ b0, const float* __restrict__ b1,
              const float* __restrict__ b2,
              float* __restrict__ Cf, __half* __restrict__ Ch, int ldc) {
    extern __shared__ char smem[];
    const uint32_t sb = smem_to_u32(smem);
    const int tid = threadIdx.x;
    const int wid = tid >> 5;
    const int lane = tid & 31;
    const int bm = blockIdx.y * BM;
    const int gn = blockIdx.x * BN;
    const int wm = (wid & 1) * 64;
    const int wn = (wid >> 1) * 32;

    auto OFF_A = [](int s) { return s * STAGE_BYTES + 0 * TILE_BYTES; };
    auto OFF_W = [](int s) { return s * STAGE_BYTES + 1 * TILE_BYTES; };

    const int fr = tid >> 1;
    const int fc0 = (tid & 1) * 2;
    const __half* gA = Ag + (size_t)(bm + fr) * DDIM;
    const __half* gW = Wg + (size_t)(gn + fr) * DDIM;

    auto fill_stage = [&](int s, int kb) {
        const int k0 = kb * BK;
        const uint32_t srow = fr * ROWB;
#pragma unroll
        for (int i = 0; i < 2; i++) {
            const int c = fc0 + i;
            const uint32_t so = srow + c * 16;
            const int go = k0 + c * 8;
            cp_async16(sb + OFF_A(s) + so, gA + go);
            cp_async16(sb + OFF_W(s) + so, gW + go);
        }
        cp_commit();
    };

    fill_stage(0, 0);
    cp_wait_all();
    __syncthreads();

    float acc[4][4][4];
#pragma unroll
    for (int i = 0; i < 4; i++)
#pragma unroll
        for (int j = 0; j < 4; j++)
#pragma unroll
            for (int q = 0; q < 4; q++) acc[i][j][q] = 0.0f;

    const uint32_t lrow = (lane & 15);
    const uint32_t lcol = (lane >> 4) * 16;

    for (int kb = 0; kb < NKB; kb++) {
        const int s = kb & 1;
        if (kb + 1 < NKB) fill_stage(s ^ 1, kb + 1);

        const uint32_t ab = sb + OFF_A(s) + (wm + lrow) * ROWB + lcol;
        const uint32_t wb = sb + OFF_W(s) + (wn + lrow) * ROWB + lcol;

#pragma unroll
        for (int ks = 0; ks < 2; ks++) {
            const uint32_t ko = ks * 32;
            uint32_t bf[2][4];
#pragma unroll
            for (int p = 0; p < 2; p++)
                ldsm_x4(bf[p], wb + p * (16 * ROWB) + ko);
#pragma unroll
            for (int mt = 0; mt < 4; mt++) {
                uint32_t af[4];
                ldsm_x4(af, ab + mt * (16 * ROWB) + ko);
#pragma unroll
                for (int nt = 0; nt < 4; nt++) {
                    const int p = nt >> 1, o = nt & 1;
                    mma16816(acc[mt][nt], af, bf[p][o], bf[p][o + 2]);
                }
            }
        }
        if (kb + 1 < NKB) cp_wait_all();
        __syncthreads();
    }

    // ---- epilogue ----
    const int g = lane >> 2, t4 = lane & 3;
    const float* bias = (blockIdx.x < 8) ? b0 : ((blockIdx.x < 16) ? b1 : b2);
    const int bb = (blockIdx.x & 7) * BN + wn;

#pragma unroll
    for (int mt = 0; mt < 4; mt++) {
        const int row0 = bm + wm + mt * 16 + g;
#pragma unroll
        for (int nt = 0; nt < 4; nt++) {
            const int col = nt * 8 + 2 * t4;
            const float bx = bias[bb + col];
            const float by = bias[bb + col + 1];
            float2 v0, v1;
            v0.x = acc[mt][nt][0] + bx;
            v0.y = acc[mt][nt][1] + by;
            v1.x = acc[mt][nt][2] + bx;
            v1.y = acc[mt][nt][3] + by;
            if (RELU) {
                v0.x = fmaxf(v0.x, 0.0f); v0.y = fmaxf(v0.y, 0.0f);
                v1.x = fmaxf(v1.x, 0.0f); v1.y = fmaxf(v1.y, 0.0f);
            }
            const size_t o0 = (size_t)row0 * ldc + gn + wn + col;
            if (F16OUT) {
                *(__half2*)(Ch + o0) = __floats2half2_rn(v0.x, v0.y);
                *(__half2*)(Ch + o0 + 8 * (size_t)ldc) = __floats2half2_rn(v1.x, v1.y);
            } else {
                *(float2*)(Cf + o0) = v0;
                *(float2*)(Cf + o0 + 8 * (size_t)ldc) = v1;
            }
        }
    }
}

// ---------------------------------------------------------------------------
// Converters
// ---------------------------------------------------------------------------
template <bool PE>
__global__ __launch_bounds__(256)
void conv_act(const float* __restrict__ x, const float* __restrict__ pe,
              __half* __restrict__ out) {
    const size_t i = ((size_t)blockIdx.x * 256 + threadIdx.x) * 4;
    float4 v = *(const float4*)(x + i);
    if (PE) {
        const int d = (int)(i & (DDIM - 1));
        v.x += pe[d + 0]; v.y += pe[d + 1]; v.z += pe[d + 2]; v.w += pe[d + 3];
    }
    __half2 h01 = __floats2half2_rn(v.x, v.y);
    __half2 h23 = __floats2half2_rn(v.z, v.w);
    *(uint2*)(out + i) = make_uint2(*(uint32_t*)&h01, *(uint32_t*)&h23);
}

// all 14 weight matrices -> fp16 arena in one launch
struct WPtrs { const float* p[14]; };

__global__ __launch_bounds__(256)
void conv_w_all(WPtrs w, __half* __restrict__ dst) {
    const size_t i = ((size_t)blockIdx.x * 256 + threadIdx.x) * 4;
    const int mat = (int)(i >> 20);
    const uint32_t off = (uint32_t)(i & ((1u << 20) - 1));
    float4 v = *(const float4*)(w.p[mat] + off);
    __half2 h01 = __floats2half2_rn(v.x, v.y);
    __half2 h23 = __floats2half2_rn(v.z, v.w);
    *(uint2*)(dst + i) = make_uint2(*(uint32_t*)&h01, *(uint32_t*)&h23);
}

// ---------------------------------------------------------------------------
// Per-position 8x8 head-mix attention (R9 version: 1 pos / 128 threads).
// fp16 strided inputs, fp16 output.
// ---------------------------------------------------------------------------
#define QROW 132

__global__ __launch_bounds__(128)
void attn_kernel(const __half* __restrict__ Q, int qs,
                 const __half* __restrict__ K, int ks_,
                 const __half* __restrict__ V, int vs,
                 __half* __restrict__ O) {
    __shared__ float sq[8 * QROW + 4];
    __shared__ float sk[8 * QROW + 4];
    __shared__ float sw[64];

    const int p = blockIdx.x;
    const int t = threadIdx.x;
    const __half* Qb = Q + (size_t)p * qs;
    const __half* Kb = K + (size_t)p * ks_;
    const __half* Vb = V + (size_t)p * vs;

    // each thread loads 8 halves (16B) of q and k, converts to fp32 smem
    {
        const int e = t * 8;
        const int i = e >> 7, h = e & 127;
        uint4 rq = *(const uint4*)(Qb + e);
        uint4 rk = *(const uint4*)(Kb + e);
        const __half2* qp = (const __half2*)&rq;
        const __half2* kp = (const __half2*)&rk;
        float* dq = sq + i * QROW + h;
        float* dk = sk + i * QROW + h;
#pragma unroll
        for (int w = 0; w < 4; w++) {
            const float2 fq = __half22float2(qp[w]);
            const float2 fk = __half22float2(kp[w]);
            dq[2 * w] = fq.x; dq[2 * w + 1] = fq.y;
            dk[2 * w] = fk.x; dk[2 * w + 1] = fk.y;
        }
    }
    __syncthreads();

    if (t < 64) {
        const int i = t >> 3, j = t & 7;
        const float* qi = &sq[i * QROW];
        const float* kj = &sk[j * QROW];
        float s = 0.0f;
#pragma unroll
        for (int h = 0; h < 128; h += 4) {
            const float4 a = *(const float4*)(qi + h);
            const float4 b = *(const float4*)(kj + h);
            s += a.x * b.x + a.y * b.y + a.z * b.z + a.w * b.w;
        }
        sw[t] = s * 0.08838834764831845f;
    }
    __syncthreads();

    if (t < 8) {
        float m = sw[t * 8];
#pragma unroll
        for (int j = 1; j < 8; j++) m = fmaxf(m, sw[t * 8 + j]);
        float s = 0.0f;
        float e[8];
#pragma unroll
        for (int j = 0; j < 8; j++) { e[j] = __expf(sw[t * 8 + j] - m); s += e[j]; }
        const float inv = 1.0f / s;
#pragma unroll
        for (int j = 0; j < 8; j++) sw[t * 8 + j] = e[j] * inv;
    }
    __syncthreads();

    float vj[8];
#pragma unroll
    for (int j = 0; j < 8; j++) vj[j] = __half2float(Vb[j * 128 + t]);
    const size_t obase = (size_t)p * 1024;
#pragma unroll
    for (int i = 0; i < 8; i++) {
        float o = 0.0f;
#pragma unroll
        for (int j = 0; j < 8; j++) o += sw[i * 8 + j] * vj[j];
        O[obase + i * 128 + t] = __float2half_rn(o);
    }
}

// ---------------------------------------------------------------------------
// Launch — two streams: s0 = default (encoder + tail), s1 = decoder-self.
// ---------------------------------------------------------------------------
extern "C" void kernel_launch(void* const* d_in, const int* in_sizes, int n_in,
                              void* d_out, int out_size) {
    const float* input_seq  = (const float*)d_in[0];
    const float* output_seq = (const float*)d_in[1];
    const float* pe         = (const float*)d_in[2];

    WPtrs wp;
    wp.p[0]  = (const float*)d_in[3];   // enc_wq
    wp.p[1]  = (const float*)d_in[5];   // enc_wk
    wp.p[2]  = (const float*)d_in[7];   // enc_wv
    wp.p[3]  = (const float*)d_in[9];   // enc_w1
    wp.p[4]  = (const float*)d_in[11];  // enc_w2
    wp.p[5]  = (const float*)d_in[13];  // dec_s_wq
    wp.p[6]  = (const float*)d_in[15];  // dec_s_wk
    wp.p[7]  = (const float*)d_in[17];  // dec_s_wv
    wp.p[8]  = (const float*)d_in[19];  // dec_c_wq
    wp.p[9]  = (const float*)d_in[21];  // dec_c_wk
    wp.p[10] = (const float*)d_in[23];  // dec_c_wv
    wp.p[11] = (const float*)d_in[25];  // dec_w1
    wp.p[12] = (const float*)d_in[27];  // dec_w2
    wp.p[13] = (const float*)d_in[29];  // fc_w
    const float* enc_bq = (const float*)d_in[4];
    const float* enc_bk = (const float*)d_in[6];
    const float* enc_bv = (const float*)d_in[8];
    const float* enc_b1 = (const float*)d_in[10];
    const float* enc_b2 = (const float*)d_in[12];
    const float* dec_s_bq = (const float*)d_in[14];
    const float* dec_s_bk = (const float*)d_in[16];
    const float* dec_s_bv = (const float*)d_in[18];
    const float* dec_c_bq = (const float*)d_in[20];
    const float* dec_c_bk = (const float*)d_in[22];
    const float* dec_c_bv = (const float*)d_in[24];
    const float* dec_b1 = (const float*)d_in[26];
    const float* dec_b2 = (const float*)d_in[28];
    const float* fc_b   = (const float*)d_in[30];

    __half *Q1, *Q2, *KVb, *Cq, *Xq, *Yq, *Aq, *Sa, *Pq, *Eq, *Ca, *WALL;
    cudaGetSymbolAddress((void**)&Q1, g_q1);
    cudaGetSymbolAddress((void**)&Q2, g_q2);
    cudaGetSymbolAddress((void**)&KVb, g_kvb);
    cudaGetSymbolAddress((void**)&Cq, g_cq);
    cudaGetSymbolAddress((void**)&Xq, g_xq);
    cudaGetSymbolAddress((void**)&Yq, g_yq);
    cudaGetSymbolAddress((void**)&Aq, g_aq);
    cudaGetSymbolAddress((void**)&Sa, g_sa);
    cudaGetSymbolAddress((void**)&Pq, g_pq);
    cudaGetSymbolAddress((void**)&Eq, g_eq);
    cudaGetSymbolAddress((void**)&Ca, g_ca);
    cudaGetSymbolAddress((void**)&WALL, g_wall);
    float* OUT = (float*)d_out;
    auto WSLOT = [&](int s) { return WALL + ((size_t)s << 20); };

    cudaFuncSetAttribute(gemm_f16<false,false>, cudaFuncAttributeMaxDynamicSharedMemorySize, GEMM_SMEM);
    cudaFuncSetAttribute(gemm_f16<false,true>,  cudaFuncAttributeMaxDynamicSharedMemorySize, GEMM_SMEM);
    cudaFuncSetAttribute(gemm_f16<true,true>,   cudaFuncAttributeMaxDynamicSharedMemorySize, GEMM_SMEM);

    static cudaStream_t s1 = nullptr;
    static cudaEvent_t evFork = nullptr, evJoin = nullptr;
    if (!s1) {
        cudaStreamCreateWithFlags(&s1, cudaStreamNonBlocking);
        cudaEventCreateWithFlags(&evFork, cudaEventDisableTiming);
        cudaEventCreateWithFlags(&evJoin, cudaEventDisableTiming);
    }

    const int CA_BLK = MDIM * DDIM / (4 * 256);   // 16384

    auto gemmH16 = [&](cudaStream_t st, int ng, const __half* a, const __half* w,
                       const float* bb0, const float* bb1, const float* bb2,
                       __half* C, int ldc, bool relu) {
        if (relu)
            gemm_f16<true,true><<<dim3(ng * 8, MDIM / BM), 256, GEMM_SMEM, st>>>(
                a, w, bb0, bb1, bb2, nullptr, C, ldc);
        else
            gemm_f16<false,true><<<dim3(ng * 8, MDIM / BM), 256, GEMM_SMEM, st>>>(
                a, w, bb0, bb1, bb2, nullptr, C, ldc);
    };

    // ---- all weights converted once, before the fork ----
    conv_w_all<<<14 * 1024, 256>>>(wp, WALL);

    // ---- fork ----
    cudaEventRecord(evFork, 0);
    cudaStreamWaitEvent(s1, evFork, 0);

    // ========== stream s1: decoder-self branch through cross-Q ==========
    conv_act<false><<<CA_BLK, 256, 0, s1>>>(output_seq, nullptr, Yq);
    gemmH16(s1, 3, Yq, WSLOT(5), dec_s_bq, dec_s_bk, dec_s_bv, Q2, 3 * DDIM, false);
    attn_kernel<<<MDIM, 128, 0, s1>>>(Q2, 3 * DDIM, Q2 + DDIM, 3 * DDIM,
                                      Q2 + 2 * DDIM, 3 * DDIM, Sa);
    gemmH16(s1, 1, Sa, WSLOT(8), dec_c_bq, dec_c_bq, dec_c_bq, Cq, DDIM, false);
    cudaEventRecord(evJoin, s1);

    // ========== stream 0: encoder branch ==========
    conv_act<true><<<CA_BLK, 256>>>(input_seq, pe, Xq);
    gemmH16(0, 3, Xq, WSLOT(0), enc_bq, enc_bk, enc_bv, Q1, 3 * DDIM, false);
    attn_kernel<<<MDIM, 128>>>(Q1, 3 * DDIM, Q1 + DDIM, 3 * DDIM,
                               Q1 + 2 * DDIM, 3 * DDIM, Aq);
    gemmH16(0, 1, Aq, WSLOT(3), enc_b1, enc_b1, enc_b1, Pq, DDIM, true);
    gemmH16(0, 1, Pq, WSLOT(4), enc_b2, enc_b2, enc_b2, Eq, DDIM, false);
    gemmH16(0, 2, Eq, WSLOT(9), dec_c_bk, dec_c_bv, dec_c_bv, KVb, 2 * DDIM, false);

    // ---- join ----
    cudaStreamWaitEvent(0, evJoin, 0);

    // ========== stream 0: cross-attn + decoder FFN + fc ==========
    attn_kernel<<<MDIM, 128>>>(Cq, DDIM, KVb, 2 * DDIM, KVb + DDIM, 2 * DDIM, Ca);
    gemmH16(0, 1, Ca, WSLOT(11), dec_b1, dec_b1, dec_b1, Pq, DDIM, true);
    gemmH16(0, 1, Pq, WSLOT(12), dec_b2, dec_b2, dec_b2, Xq, DDIM, false);
    gemm_f16<false,false><<<dim3(8, MDIM / BM), 256, GEMM_SMEM>>>(
        Xq, WSLOT(13), fc_b, fc_b, fc_b, OUT, nullptr, DDIM);
}

// round 12
// speedup vs baseline: 1.0522x; 1.0279x over previous
#include <cuda_runtime.h>
#include <cuda_fp16.h>
#include <cstdint>

// ---------------------------------------------------------------------------
// DialogueTransformer on GB300 (sm_103a, base sm_103 PTX => legacy mma.sync).
// R12: M-split pipelining. The network is fully per-row (attention is
// per-position head mixing), so rows [0,8192) and [8192,16384) run the entire
// encoder+decoder chain independently on two streams. Memory-bound stages of
// one half overlap tensor-bound GEMMs of the other.
// GEMM engine unchanged (single-product fp16 HMMA at the legacy-pipe floor).
// ---------------------------------------------------------------------------

#define MDIM 16384
#define DDIM 1024
#define MHALF (MDIM / 2)

// fp16 activation buffers
__device__ __align__(256) __half g_q1[MDIM * 3 * DDIM];   // enc QKV
__device__ __align__(256) __half g_q2[MDIM * 3 * DDIM];   // dec-self QKV
__device__ __align__(256) __half g_kvb[MDIM * 2 * DDIM];  // cross K,V
__device__ __align__(256) __half g_cq[MDIM * DDIM];       // cross Q
__device__ __align__(256) __half g_xq[MDIM * DDIM];       // enc input / dec ffn2 out
__device__ __align__(256) __half g_yq[MDIM * DDIM];       // dec input
__device__ __align__(256) __half g_aq[MDIM * DDIM];       // enc attn out
__device__ __align__(256) __half g_sa[MDIM * DDIM];       // dec self-attn out
__device__ __align__(256) __half g_pq[MDIM * DDIM];       // ffn hidden
__device__ __align__(256) __half g_eq[MDIM * DDIM];       // enc_out
__device__ __align__(256) __half g_ca[MDIM * DDIM];       // cross attn out
// single fp16 weight arena: 14 slots of 1M halves
// slots: 0-2 enc qkv | 3 enc w1 | 4 enc w2 | 5-7 dec_s qkv | 8 dec_c q
//        9-10 dec_c k,v | 11 dec w1 | 12 dec w2 | 13 fc
__device__ __align__(256) __half g_wall[14u << 20];

// ---------------------------------------------------------------------------
// PTX helpers (baseline sm_80+ PTX only)
// ---------------------------------------------------------------------------
__device__ __forceinline__ uint32_t smem_to_u32(const void* p) {
    uint32_t a;
    asm("{ .reg .u64 t; cvta.to.shared.u64 t, %1; cvt.u32.u64 %0, t; }" : "=r"(a) : "l"(p));
    return a;
}
__device__ __forceinline__ void cp_async16(uint32_t saddr, const void* gptr) {
    asm volatile("cp.async.cg.shared.global [%0], [%1], 16;" :: "r"(saddr), "l"(gptr));
}
__device__ __forceinline__ void cp_commit() { asm volatile("cp.async.commit_group;"); }
__device__ __forceinline__ void cp_wait_all() { asm volatile("cp.async.wait_group 0;" ::: "memory"); }

__device__ __forceinline__ void ldsm_x4(uint32_t* r, uint32_t addr) {
    asm volatile("ldmatrix.sync.aligned.m8n8.x4.shared.b16 {%0,%1,%2,%3}, [%4];"
                 : "=r"(r[0]), "=r"(r[1]), "=r"(r[2]), "=r"(r[3]) : "r"(addr));
}
__device__ __forceinline__ void mma16816(float* c, const uint32_t* a,
                                         uint32_t b0, uint32_t b1) {
    asm volatile(
        "mma.sync.aligned.m16n8k16.row.col.f32.f16.f16.f32 "
        "{%0,%1,%2,%3}, {%4,%5,%6,%7}, {%8,%9}, {%0,%1,%2,%3};"
        : "+f"(c[0]), "+f"(c[1]), "+f"(c[2]), "+f"(c[3])
        : "r"(a[0]), "r"(a[1]), "r"(a[2]), "r"(a[3]), "r"(b0), "r"(b1));
}

// ---------------------------------------------------------------------------
// fp16 GEMM: C[m,gn] = sum_k a[m,k]*w[gn,k] + bias(gn)
// BM=128, BN=128, BK=32 halves, 256 thr, 8 warps (2x4 -> 64x32 warp tiles).
// ---------------------------------------------------------------------------
#define BM 128
#define BN 128
#define BK 32
#define NKB (DDIM / BK)   // 32
#define ROWB 80
#define TILE_BYTES (128 * ROWB)          // 10240
#define STAGE_BYTES (2 * TILE_BYTES)     // A, W = 20480
#define GEMM_SMEM (2 * STAGE_BYTES)      // 40960

template <bool RELU, bool F16OUT>
__global__ __launch_bounds__(256, 2)
void gemm_f16(const __half* __restrict__ Ag,
              const __half* __restrict__ Wg,
              const float* __restrict__ b0, const float* __restrict__ b1,
              const float* __restrict__ b2,
              float* __restrict__ Cf, __half* __restrict__ Ch, int ldc) {
    extern __shared__ char smem[];
    const uint32_t sb = smem_to_u32(smem);
    const int tid = threadIdx.x;
    const int wid = tid >> 5;
    const int lane = tid & 31;
    const int bm = blockIdx.y * BM;
    const int gn = blockIdx.x * BN;
    const int wm = (wid & 1) * 64;
    const int wn = (wid >> 1) * 32;

    auto OFF_A = [](int s) { return s * STAGE_BYTES + 0 * TILE_BYTES; };
    auto OFF_W = [](int s) { return s * STAGE_BYTES + 1 * TILE_BYTES; };

    const int fr = tid >> 1;
    const int fc0 = (tid & 1) * 2;
    const __half* gA = Ag + (size_t)(bm + fr) * DDIM;
    const __half* gW = Wg + (size_t)(gn + fr) * DDIM;

    auto fill_stage = [&](int s, int kb) {
        const int k0 = kb * BK;
        const uint32_t srow = fr * ROWB;
#pragma unroll
        for (int i = 0; i < 2; i++) {
            const int c = fc0 + i;
            const uint32_t so = srow + c * 16;
            const int go = k0 + c * 8;
            cp_async16(sb + OFF_A(s) + so, gA + go);
            cp_async16(sb + OFF_W(s) + so, gW + go);
        }
        cp_commit();
    };

    fill_stage(0, 0);
    cp_wait_all();
    __syncthreads();

    float acc[4][4][4];
#pragma unroll
    for (int i = 0; i < 4; i++)
#pragma unroll
        for (int j = 0; j < 4; j++)
#pragma unroll
            for (int q = 0; q < 4; q++) acc[i][j][q] = 0.0f;

    const uint32_t lrow = (lane & 15);
    const uint32_t lcol = (lane >> 4) * 16;

    for (int kb = 0; kb < NKB; kb++) {
        const int s = kb & 1;
        if (kb + 1 < NKB) fill_stage(s ^ 1, kb + 1);

        const uint32_t ab = sb + OFF_A(s) + (wm + lrow) * ROWB + lcol;
        const uint32_t wb = sb + OFF_W(s) + (wn + lrow) * ROWB + lcol;

#pragma unroll
        for (int ks = 0; ks < 2; ks++) {
            const uint32_t ko = ks * 32;
            uint32_t bf[2][4];
#pragma unroll
            for (int p = 0; p < 2; p++)
                ldsm_x4(bf[p], wb + p * (16 * ROWB) + ko);
#pragma unroll
            for (int mt = 0; mt < 4; mt++) {
                uint32_t af[4];
                ldsm_x4(af, ab + mt * (16 * ROWB) + ko);
#pragma unroll
                for (int nt = 0; nt < 4; nt++) {
                    const int p = nt >> 1, o = nt & 1;
                    mma16816(acc[mt][nt], af, bf[p][o], bf[p][o + 2]);
                }
            }
        }
        if (kb + 1 < NKB) cp_wait_all();
        __syncthreads();
    }

    // ---- epilogue ----
    const int g = lane >> 2, t4 = lane & 3;
    const float* bias = (blockIdx.x < 8) ? b0 : ((blockIdx.x < 16) ? b1 : b2);
    const int bb = (blockIdx.x & 7) * BN + wn;

#pragma unroll
    for (int mt = 0; mt < 4; mt++) {
        const int row0 = bm + wm + mt * 16 + g;
#pragma unroll
        for (int nt = 0; nt < 4; nt++) {
            const int col = nt * 8 + 2 * t4;
            const float bx = bias[bb + col];
            const float by = bias[bb + col + 1];
            float2 v0, v1;
            v0.x = acc[mt][nt][0] + bx;
            v0.y = acc[mt][nt][1] + by;
            v1.x = acc[mt][nt][2] + bx;
            v1.y = acc[mt][nt][3] + by;
            if (RELU) {
                v0.x = fmaxf(v0.x, 0.0f); v0.y = fmaxf(v0.y, 0.0f);
                v1.x = fmaxf(v1.x, 0.0f); v1.y = fmaxf(v1.y, 0.0f);
            }
            const size_t o0 = (size_t)row0 * ldc + gn + wn + col;
            if (F16OUT) {
                *(__half2*)(Ch + o0) = __floats2half2_rn(v0.x, v0.y);
                *(__half2*)(Ch + o0 + 8 * (size_t)ldc) = __floats2half2_rn(v1.x, v1.y);
            } else {
                *(float2*)(Cf + o0) = v0;
                *(float2*)(Cf + o0 + 8 * (size_t)ldc) = v1;
            }
        }
    }
}

// ---------------------------------------------------------------------------
// Converters
// ---------------------------------------------------------------------------
template <bool PE>
__global__ __launch_bounds__(256)
void conv_act(const float* __restrict__ x, const float* __restrict__ pe,
              __half* __restrict__ out) {
    const size_t i = ((size_t)blockIdx.x * 256 + threadIdx.x) * 4;
    float4 v = *(const float4*)(x + i);
    if (PE) {
        const int d = (int)(i & (DDIM - 1));
        v.x += pe[d + 0]; v.y += pe[d + 1]; v.z += pe[d + 2]; v.w += pe[d + 3];
    }
    __half2 h01 = __floats2half2_rn(v.x, v.y);
    __half2 h23 = __floats2half2_rn(v.z, v.w);
    *(uint2*)(out + i) = make_uint2(*(uint32_t*)&h01, *(uint32_t*)&h23);
}

// all 14 weight matrices -> fp16 arena in one launch
struct WPtrs { const float* p[14]; };

__global__ __launch_bounds__(256)
void conv_w_all(WPtrs w, __half* __restrict__ dst) {
    const size_t i = ((size_t)blockIdx.x * 256 + threadIdx.x) * 4;
    const int mat = (int)(i >> 20);
    const uint32_t off = (uint32_t)(i & ((1u << 20) - 1));
    float4 v = *(const float4*)(w.p[mat] + off);
    __half2 h01 = __floats2half2_rn(v.x, v.y);
    __half2 h23 = __floats2half2_rn(v.z, v.w);
    *(uint2*)(dst + i) = make_uint2(*(uint32_t*)&h01, *(uint32_t*)&h23);
}

// ---------------------------------------------------------------------------
// Per-position 8x8 head-mix attention (1 pos / 128 threads).
// fp16 strided inputs, fp16 output.
// ---------------------------------------------------------------------------
#define QROW 132

__global__ __launch_bounds__(128)
void attn_kernel(const __half* __restrict__ Q, int qs,
                 const __half* __restrict__ K, int ks_,
                 const __half* __restrict__ V, int vs,
                 __half* __restrict__ O) {
    __shared__ float sq[8 * QROW + 4];
    __shared__ float sk[8 * QROW + 4];
    __shared__ float sw[64];

    const int p = blockIdx.x;
    const int t = threadIdx.x;
    const __half* Qb = Q + (size_t)p * qs;
    const __half* Kb = K + (size_t)p * ks_;
    const __half* Vb = V + (size_t)p * vs;

    {
        const int e = t * 8;
        const int i = e >> 7, h = e & 127;
        uint4 rq = *(const uint4*)(Qb + e);
        uint4 rk = *(const uint4*)(Kb + e);
        const __half2* qp = (const __half2*)&rq;
        const __half2* kp = (const __half2*)&rk;
        float* dq = sq + i * QROW + h;
        float* dk = sk + i * QROW + h;
#pragma unroll
        for (int w = 0; w < 4; w++) {
            const float2 fq = __half22float2(qp[w]);
            const float2 fk = __half22float2(kp[w]);
            dq[2 * w] = fq.x; dq[2 * w + 1] = fq.y;
            dk[2 * w] = fk.x; dk[2 * w + 1] = fk.y;
        }
    }
    __syncthreads();

    if (t < 64) {
        const int i = t >> 3, j = t & 7;
        const float* qi = &sq[i * QROW];
        const float* kj = &sk[j * QROW];
        float s = 0.0f;
#pragma unroll
        for (int h = 0; h < 128; h += 4) {
            const float4 a = *(const float4*)(qi + h);
            const float4 b = *(const float4*)(kj + h);
            s += a.x * b.x + a.y * b.y + a.z * b.z + a.w * b.w;
        }
        sw[t] = s * 0.08838834764831845f;
    }
    __syncthreads();

    if (t < 8) {
        float m = sw[t * 8];
#pragma unroll
        for (int j = 1; j < 8; j++) m = fmaxf(m, sw[t * 8 + j]);
        float s = 0.0f;
        float e[8];
#pragma unroll
        for (int j = 0; j < 8; j++) { e[j] = __expf(sw[t * 8 + j] - m); s += e[j]; }
        const float inv = 1.0f / s;
#pragma unroll
        for (int j = 0; j < 8; j++) sw[t * 8 + j] = e[j] * inv;
    }
    __syncthreads();

    float vj[8];
#pragma unroll
    for (int j = 0; j < 8; j++) vj[j] = __half2float(Vb[j * 128 + t]);
    const size_t obase = (size_t)p * 1024;
#pragma unroll
    for (int i = 0; i < 8; i++) {
        float o = 0.0f;
#pragma unroll
        for (int j = 0; j < 8; j++) o += sw[i * 8 + j] * vj[j];
        O[obase + i * 128 + t] = __float2half_rn(o);
    }
}

// ---------------------------------------------------------------------------
// Launch — rows [0,8192) on stream 0, rows [8192,16384) on stream s1;
// each runs the complete network on its half (fully independent per-row).
// ---------------------------------------------------------------------------
extern "C" void kernel_launch(void* const* d_in, const int* in_sizes, int n_in,
                              void* d_out, int out_size) {
    const float* input_seq  = (const float*)d_in[0];
    const float* output_seq = (const float*)d_in[1];
    const float* pe         = (const float*)d_in[2];

    WPtrs wp;
    wp.p[0]  = (const float*)d_in[3];   // enc_wq
    wp.p[1]  = (const float*)d_in[5];   // enc_wk
    wp.p[2]  = (const float*)d_in[7];   // enc_wv
    wp.p[3]  = (const float*)d_in[9];   // enc_w1
    wp.p[4]  = (const float*)d_in[11];  // enc_w2
    wp.p[5]  = (const float*)d_in[13];  // dec_s_wq
    wp.p[6]  = (const float*)d_in[15];  // dec_s_wk
    wp.p[7]  = (const float*)d_in[17];  // dec_s_wv
    wp.p[8]  = (const float*)d_in[19];  // dec_c_wq
    wp.p[9]  = (const float*)d_in[21];  // dec_c_wk
    wp.p[10] = (const float*)d_in[23];  // dec_c_wv
    wp.p[11] = (const float*)d_in[25];  // dec_w1
    wp.p[12] = (const float*)d_in[27];  // dec_w2
    wp.p[13] = (const float*)d_in[29];  // fc_w
    const float* enc_bq = (const float*)d_in[4];
    const float* enc_bk = (const float*)d_in[6];
    const float* enc_bv = (const float*)d_in[8];
    const float* enc_b1 = (const float*)d_in[10];
    const float* enc_b2 = (const float*)d_in[12];
    const float* dec_s_bq = (const float*)d_in[14];
    const float* dec_s_bk = (const float*)d_in[16];
    const float* dec_s_bv = (const float*)d_in[18];
    const float* dec_c_bq = (const float*)d_in[20];
    const float* dec_c_bk = (const float*)d_in[22];
    const float* dec_c_bv = (const float*)d_in[24];
    const float* dec_b1 = (const float*)d_in[26];
    const float* dec_b2 = (const float*)d_in[28];
    const float* fc_b   = (const float*)d_in[30];

    __half *Q1, *Q2, *KVb, *Cq, *Xq, *Yq, *Aq, *Sa, *Pq, *Eq, *Ca, *WALL;
    cudaGetSymbolAddress((void**)&Q1, g_q1);
    cudaGetSymbolAddress((void**)&Q2, g_q2);
    cudaGetSymbolAddress((void**)&KVb, g_kvb);
    cudaGetSymbolAddress((void**)&Cq, g_cq);
    cudaGetSymbolAddress((void**)&Xq, g_xq);
    cudaGetSymbolAddress((void**)&Yq, g_yq);
    cudaGetSymbolAddress((void**)&Aq, g_aq);
    cudaGetSymbolAddress((void**)&Sa, g_sa);
    cudaGetSymbolAddress((void**)&Pq, g_pq);
    cudaGetSymbolAddress((void**)&Eq, g_eq);
    cudaGetSymbolAddress((void**)&Ca, g_ca);
    cudaGetSymbolAddress((void**)&WALL, g_wall);
    float* OUT = (float*)d_out;
    auto WSLOT = [&](int s) { return WALL + ((size_t)s << 20); };

    cudaFuncSetAttribute(gemm_f16<false,false>, cudaFuncAttributeMaxDynamicSharedMemorySize, GEMM_SMEM);
    cudaFuncSetAttribute(gemm_f16<false,true>,  cudaFuncAttributeMaxDynamicSharedMemorySize, GEMM_SMEM);
    cudaFuncSetAttribute(gemm_f16<true,true>,   cudaFuncAttributeMaxDynamicSharedMemorySize, GEMM_SMEM);

    static cudaStream_t s1 = nullptr;
    static cudaEvent_t evFork = nullptr, evJoin = nullptr;
    if (!s1) {
        cudaStreamCreateWithFlags(&s1, cudaStreamNonBlocking);
        cudaEventCreateWithFlags(&evFork, cudaEventDisableTiming);
        cudaEventCreateWithFlags(&evJoin, cudaEventDisableTiming);
    }

    // ---- all weights converted once (serial head, ~15us) ----
    conv_w_all<<<14 * 1024, 256>>>(wp, WALL);
    cudaEventRecord(evFork, 0);
    cudaStreamWaitEvent(s1, evFork, 0);

    const int CA_HALF = MHALF * DDIM / (4 * 256);   // 8192 blocks
    const dim3 GY(8, MHALF / BM);                    // base grid for ng=1

    // run the full network on rows [r, r+MHALF) on stream st
    auto run_half = [&](cudaStream_t st, int r) {
        const size_t rD  = (size_t)r * DDIM;
        const size_t r2D = (size_t)r * 2 * DDIM;
        const size_t r3D = (size_t)r * 3 * DDIM;

        auto g = [&](int ng, const __half* a, int slot,
                     const float* bb0, const float* bb1, const float* bb2,
                     __half* C, int ldc, bool relu) {
            const dim3 grid(ng * 8, MHALF / BM);
            if (relu)
                gemm_f16<true,true><<<grid, 256, GEMM_SMEM, st>>>(
                    a, WSLOT(slot), bb0, bb1, bb2, nullptr, C, ldc);
            else
                gemm_f16<false,true><<<grid, 256, GEMM_SMEM, st>>>(
                    a, WSLOT(slot), bb0, bb1, bb2, nullptr, C, ldc);
        };

        // encoder
        conv_act<true><<<CA_HALF, 256, 0, st>>>(input_seq + rD, pe, Xq + rD);
        g(3, Xq + rD, 0, enc_bq, enc_bk, enc_bv, Q1 + r3D, 3 * DDIM, false);
        attn_kernel<<<MHALF, 128, 0, st>>>(Q1 + r3D, 3 * DDIM, Q1 + r3D + DDIM, 3 * DDIM,
                                           Q1 + r3D + 2 * DDIM, 3 * DDIM, Aq + rD);
        g(1, Aq + rD, 3, enc_b1, enc_b1, enc_b1, Pq + rD, DDIM, true);
        g(1, Pq + rD, 4, enc_b2, enc_b2, enc_b2, Eq + rD, DDIM, false);
        g(2, Eq + rD, 9, dec_c_bk, dec_c_bv, dec_c_bv, KVb + r2D, 2 * DDIM, false);

        // decoder self-attn
        conv_act<false><<<CA_HALF, 256, 0, st>>>(output_seq + rD, nullptr, Yq + rD);
        g(3, Yq + rD, 5, dec_s_bq, dec_s_bk, dec_s_bv, Q2 + r3D, 3 * DDIM, false);
        attn_kernel<<<MHALF, 128, 0, st>>>(Q2 + r3D, 3 * DDIM, Q2 + r3D + DDIM, 3 * DDIM,
                                           Q2 + r3D + 2 * DDIM, 3 * DDIM, Sa + rD);
        g(1, Sa + rD, 8, dec_c_bq, dec_c_bq, dec_c_bq, Cq + rD, DDIM, false);

        // cross-attn + decoder FFN + fc
        attn_kernel<<<MHALF, 128, 0, st>>>(Cq + rD, DDIM, KVb + r2D, 2 * DDIM,
                                           KVb + r2D + DDIM, 2 * DDIM, Ca + rD);
        g(1, Ca + rD, 11, dec_b1, dec_b1, dec_b1, Pq + rD, DDIM, true);
        g(1, Pq + rD, 12, dec_b2, dec_b2, dec_b2, Xq + rD, DDIM, false);
        gemm_f16<false,false><<<GY, 256, GEMM_SMEM, st>>>(
            Xq + rD, WSLOT(13), fc_b, fc_b, fc_b, OUT + rD, nullptr, DDIM);
    };

    run_half(0, 0);           // rows [0, 8192) on default stream
    run_half(s1, MHALF);      // rows [8192, 16384) on s1

    // join: stream 0 waits for s1's half before the graph's end
    cudaEventRecord(evJoin, s1);
    cudaStreamWaitEvent(0, evJoin, 0);
}

// round 13
// speedup vs baseline: 1.0537x; 1.0014x over previous
#include <cuda_runtime.h>
#include <cuda_fp16.h>
#include <cstdint>

// ---------------------------------------------------------------------------
// DialogueTransformer on GB300 (sm_103a, base sm_103 PTX => legacy mma.sync).
// R12: M-split pipelining. The network is fully per-row (attention is
// per-position head mixing), so rows [0,8192) and [8192,16384) run the entire
// encoder+decoder chain independently on two streams. Memory-bound stages of
// one half overlap tensor-bound GEMMs of the other.
// GEMM engine unchanged (single-product fp16 HMMA at the legacy-pipe floor).
// ---------------------------------------------------------------------------

#define MDIM 16384
#define DDIM 1024
#define MHALF (MDIM / 2)

// fp16 activation buffers
__device__ __align__(256) __half g_q1[MDIM * 3 * DDIM];   // enc QKV
__device__ __align__(256) __half g_q2[MDIM * 3 * DDIM];   // dec-self QKV
__device__ __align__(256) __half g_kvb[MDIM * 2 * DDIM];  // cross K,V
__device__ __align__(256) __half g_cq[MDIM * DDIM];       // cross Q
__device__ __align__(256) __half g_xq[MDIM * DDIM];       // enc input / dec ffn2 out
__device__ __align__(256) __half g_yq[MDIM * DDIM];       // dec input
__device__ __align__(256) __half g_aq[MDIM * DDIM];       // enc attn out
__device__ __align__(256) __half g_sa[MDIM * DDIM];       // dec self-attn out
__device__ __align__(256) __half g_pq[MDIM * DDIM];       // ffn hidden
__device__ __align__(256) __half g_eq[MDIM * DDIM];       // enc_out
__device__ __align__(256) __half g_ca[MDIM * DDIM];       // cross attn out
// single fp16 weight arena: 14 slots of 1M halves
// slots: 0-2 enc qkv | 3 enc w1 | 4 enc w2 | 5-7 dec_s qkv | 8 dec_c q
//        9-10 dec_c k,v | 11 dec w1 | 12 dec w2 | 13 fc
__device__ __align__(256) __half g_wall[14u << 20];

// ---------------------------------------------------------------------------
// PTX helpers (baseline sm_80+ PTX only)
// ---------------------------------------------------------------------------
__device__ __forceinline__ uint32_t smem_to_u32(const void* p) {
    uint32_t a;
    asm("{ .reg .u64 t; cvta.to.shared.u64 t, %1; cvt.u32.u64 %0, t; }" : "=r"(a) : "l"(p));
    return a;
}
__device__ __forceinline__ void cp_async16(uint32_t saddr, const void* gptr) {
    asm volatile("cp.async.cg.shared.global [%0], [%1], 16;" :: "r"(saddr), "l"(gptr));
}
__device__ __forceinline__ void cp_commit() { asm volatile("cp.async.commit_group;"); }
__device__ __forceinline__ void cp_wait_all() { asm volatile("cp.async.wait_group 0;" ::: "memory"); }

__device__ __forceinline__ void ldsm_x4(uint32_t* r, uint32_t addr) {
    asm volatile("ldmatrix.sync.aligned.m8n8.x4.shared.b16 {%0,%1,%2,%3}, [%4];"
                 : "=r"(r[0]), "=r"(r[1]), "=r"(r[2]), "=r"(r[3]) : "r"(addr));
}
__device__ __forceinline__ void mma16816(float* c, const uint32_t* a,
                                         uint32_t b0, uint32_t b1) {
    asm volatile(
        "mma.sync.aligned.m16n8k16.row.col.f32.f16.f16.f32 "
        "{%0,%1,%2,%3}, {%4,%5,%6,%7}, {%8,%9}, {%0,%1,%2,%3};"
        : "+f"(c[0]), "+f"(c[1]), "+f"(c[2]), "+f"(c[3])
        : "r"(a[0]), "r"(a[1]), "r"(a[2]), "r"(a[3]), "r"(b0), "r"(b1));
}

// ---------------------------------------------------------------------------
// fp16 GEMM: C[m,gn] = sum_k a[m,k]*w[gn,k] + bias(gn)
// BM=128, BN=128, BK=32 halves, 256 thr, 8 warps (2x4 -> 64x32 warp tiles).
// ---------------------------------------------------------------------------
#define BM 128
#define BN 128
#define BK 32
#define NKB (DDIM / BK)   // 32
#define ROWB 80
#define TILE_BYTES (128 * ROWB)          // 10240
#define STAGE_BYTES (2 * TILE_BYTES)     // A, W = 20480
#define GEMM_SMEM (2 * STAGE_BYTES)      // 40960

template <bool RELU, bool F16OUT>
__global__ __launch_bounds__(256, 2)
void gemm_f16(const __half* __restrict__ Ag,
              const __half* __restrict__ Wg,
              const float* __restrict__ b0, const float* __restrict__ b1,
              const float* __restrict__ b2,
              float* __restrict__ Cf, __half* __restrict__ Ch, int ldc) {
    extern __shared__ char smem[];
    const uint32_t sb = smem_to_u32(smem);
    const int tid = threadIdx.x;
    const int wid = tid >> 5;
    const int lane = tid & 31;
    const int bm = blockIdx.y * BM;
    const int gn = blockIdx.x * BN;
    const int wm = (wid & 1) * 64;
    const int wn = (wid >> 1) * 32;

    auto OFF_A = [](int s) { return s * STAGE_BYTES + 0 * TILE_BYTES; };
    auto OFF_W = [](int s) { return s * STAGE_BYTES + 1 * TILE_BYTES; };

    const int fr = tid >> 1;
    const int fc0 = (tid & 1) * 2;
    const __half* gA = Ag + (size_t)(bm + fr) * DDIM;
    const __half* gW = Wg + (size_t)(gn + fr) * DDIM;

    auto fill_stage = [&](int s, int kb) {
        const int k0 = kb * BK;
        const uint32_t srow = fr * ROWB;
#pragma unroll
        for (int i = 0; i < 2; i++) {
            const int c = fc0 + i;
            const uint32_t so = srow + c * 16;
            const int go = k0 + c * 8;
            cp_async16(sb + OFF_A(s) + so, gA + go);
            cp_async16(sb + OFF_W(s) + so, gW + go);
        }
        cp_commit();
    };

    fill_stage(0, 0);
    cp_wait_all();
    __syncthreads();

    float acc[4][4][4];
#pragma unroll
    for (int i = 0; i < 4; i++)
#pragma unroll
        for (int j = 0; j < 4; j++)
#pragma unroll
            for (int q = 0; q < 4; q++) acc[i][j][q] = 0.0f;

    const uint32_t lrow = (lane & 15);
    const uint32_t lcol = (lane >> 4) * 16;

    for (int kb = 0; kb < NKB; kb++) {
        const int s = kb & 1;
        if (kb + 1 < NKB) fill_stage(s ^ 1, kb + 1);

        const uint32_t ab = sb + OFF_A(s) + (wm + lrow) * ROWB + lcol;
        const uint32_t wb = sb + OFF_W(s) + (wn + lrow) * ROWB + lcol;

#pragma unroll
        for (int ks = 0; ks < 2; ks++) {
            const uint32_t ko = ks * 32;
            uint32_t bf[2][4];
#pragma unroll
            for (int p = 0; p < 2; p++)
                ldsm_x4(bf[p], wb + p * (16 * ROWB) + ko);
#pragma unroll
            for (int mt = 0; mt < 4; mt++) {
                uint32_t af[4];
                ldsm_x4(af, ab + mt * (16 * ROWB) + ko);
#pragma unroll
                for (int nt = 0; nt < 4; nt++) {
                    const int p = nt >> 1, o = nt & 1;
                    mma16816(acc[mt][nt], af, bf[p][o], bf[p][o + 2]);
                }
            }
        }
        if (kb + 1 < NKB) cp_wait_all();
        __syncthreads();
    }

    // ---- epilogue ----
    const int g = lane >> 2, t4 = lane & 3;
    const float* bias = (blockIdx.x < 8) ? b0 : ((blockIdx.x < 16) ? b1 : b2);
    const int bb = (blockIdx.x & 7) * BN + wn;

#pragma unroll
    for (int mt = 0; mt < 4; mt++) {
        const int row0 = bm + wm + mt * 16 + g;
#pragma unroll
        for (int nt = 0; nt < 4; nt++) {
            const int col = nt * 8 + 2 * t4;
            const float bx = bias[bb + col];
            const float by = bias[bb + col + 1];
            float2 v0, v1;
            v0.x = acc[mt][nt][0] + bx;
            v0.y = acc[mt][nt][1] + by;
            v1.x = acc[mt][nt][2] + bx;
            v1.y = acc[mt][nt][3] + by;
            if (RELU) {
                v0.x = fmaxf(v0.x, 0.0f); v0.y = fmaxf(v0.y, 0.0f);
                v1.x = fmaxf(v1.x, 0.0f); v1.y = fmaxf(v1.y, 0.0f);
            }
            const size_t o0 = (size_t)row0 * ldc + gn + wn + col;
            if (F16OUT) {
                *(__half2*)(Ch + o0) = __floats2half2_rn(v0.x, v0.y);
                *(__half2*)(Ch + o0 + 8 * (size_t)ldc) = __floats2half2_rn(v1.x, v1.y);
            } else {
                *(float2*)(Cf + o0) = v0;
                *(float2*)(Cf + o0 + 8 * (size_t)ldc) = v1;
            }
        }
    }
}

// ---------------------------------------------------------------------------
// Converters
// ---------------------------------------------------------------------------
template <bool PE>
__global__ __launch_bounds__(256)
void conv_act(const float* __restrict__ x, const float* __restrict__ pe,
              __half* __restrict__ out) {
    const size_t i = ((size_t)blockIdx.x * 256 + threadIdx.x) * 4;
    float4 v = *(const float4*)(x + i);
    if (PE) {
        const int d = (int)(i & (DDIM - 1));
        v.x += pe[d + 0]; v.y += pe[d + 1]; v.z += pe[d + 2]; v.w += pe[d + 3];
    }
    __half2 h01 = __floats2half2_rn(v.x, v.y);
    __half2 h23 = __floats2half2_rn(v.z, v.w);
    *(uint2*)(out + i) = make_uint2(*(uint32_t*)&h01, *(uint32_t*)&h23);
}

// all 14 weight matrices -> fp16 arena in one launch
struct WPtrs { const float* p[14]; };

__global__ __launch_bounds__(256)
void conv_w_all(WPtrs w, __half* __restrict__ dst) {
    const size_t i = ((size_t)blockIdx.x * 256 + threadIdx.x) * 4;
    const int mat = (int)(i >> 20);
    const uint32_t off = (uint32_t)(i & ((1u << 20) - 1));
    float4 v = *(const float4*)(w.p[mat] + off);
    __half2 h01 = __floats2half2_rn(v.x, v.y);
    __half2 h23 = __floats2half2_rn(v.z, v.w);
    *(uint2*)(dst + i) = make_uint2(*(uint32_t*)&h01, *(uint32_t*)&h23);
}

// ---------------------------------------------------------------------------
// Per-position 8x8 head-mix attention (1 pos / 128 threads).
// fp16 strided inputs, fp16 output.
// ---------------------------------------------------------------------------
#define QROW 132

__global__ __launch_bounds__(128)
void attn_kernel(const __half* __restrict__ Q, int qs,
                 const __half* __restrict__ K, int ks_,
                 const __half* __restrict__ V, int vs,
                 __half* __restrict__ O) {
    __shared__ float sq[8 * QROW + 4];
    __shared__ float sk[8 * QROW + 4];
    __shared__ float sw[64];

    const int p = blockIdx.x;
    const int t = threadIdx.x;
    const __half* Qb = Q + (size_t)p * qs;
    const __half* Kb = K + (size_t)p * ks_;
    const __half* Vb = V + (size_t)p * vs;

    {
        const int e = t * 8;
        const int i = e >> 7, h = e & 127;
        uint4 rq = *(const uint4*)(Qb + e);
        uint4 rk = *(const uint4*)(Kb + e);
        const __half2* qp = (const __half2*)&rq;
        const __half2* kp = (const __half2*)&rk;
        float* dq = sq + i * QROW + h;
        float* dk = sk + i * QROW + h;
#pragma unroll
        for (int w = 0; w < 4; w++) {
            const float2 fq = __half22float2(qp[w]);
            const float2 fk = __half22float2(kp[w]);
            dq[2 * w] = fq.x; dq[2 * w + 1] = fq.y;
            dk[2 * w] = fk.x; dk[2 * w + 1] = fk.y;
        }
    }
    __syncthreads();

    if (t < 64) {
        const int i = t >> 3, j = t & 7;
        const float* qi = &sq[i * QROW];
        const float* kj = &sk[j * QROW];
        float s = 0.0f;
#pragma unroll
        for (int h = 0; h < 128; h += 4) {
            const float4 a = *(const float4*)(qi + h);
            const float4 b = *(const float4*)(kj + h);
            s += a.x * b.x + a.y * b.y + a.z * b.z + a.w * b.w;
        }
        sw[t] = s * 0.08838834764831845f;
    }
    __syncthreads();

    if (t < 8) {
        float m = sw[t * 8];
#pragma unroll
        for (int j = 1; j < 8; j++) m = fmaxf(m, sw[t * 8 + j]);
        float s = 0.0f;
        float e[8];
#pragma unroll
        for (int j = 0; j < 8; j++) { e[j] = __expf(sw[t * 8 + j] - m); s += e[j]; }
        const float inv = 1.0f / s;
#pragma unroll
        for (int j = 0; j < 8; j++) sw[t * 8 + j] = e[j] * inv;
    }
    __syncthreads();

    float vj[8];
#pragma unroll
    for (int j = 0; j < 8; j++) vj[j] = __half2float(Vb[j * 128 + t]);
    const size_t obase = (size_t)p * 1024;
#pragma unroll
    for (int i = 0; i < 8; i++) {
        float o = 0.0f;
#pragma unroll
        for (int j = 0; j < 8; j++) o += sw[i * 8 + j] * vj[j];
        O[obase + i * 128 + t] = __float2half_rn(o);
    }
}

// ---------------------------------------------------------------------------
// Launch — rows [0,8192) on stream 0, rows [8192,16384) on stream s1;
// each runs the complete network on its half (fully independent per-row).
// ---------------------------------------------------------------------------
extern "C" void kernel_launch(void* const* d_in, const int* in_sizes, int n_in,
                              void* d_out, int out_size) {
    const float* input_seq  = (const float*)d_in[0];
    const float* output_seq = (const float*)d_in[1];
    const float* pe         = (const float*)d_in[2];

    WPtrs wp;
    wp.p[0]  = (const float*)d_in[3];   // enc_wq
    wp.p[1]  = (const float*)d_in[5];   // enc_wk
    wp.p[2]  = (const float*)d_in[7];   // enc_wv
    wp.p[3]  = (const float*)d_in[9];   // enc_w1
    wp.p[4]  = (const float*)d_in[11];  // enc_w2
    wp.p[5]  = (const float*)d_in[13];  // dec_s_wq
    wp.p[6]  = (const float*)d_in[15];  // dec_s_wk
    wp.p[7]  = (const float*)d_in[17];  // dec_s_wv
    wp.p[8]  = (const float*)d_in[19];  // dec_c_wq
    wp.p[9]  = (const float*)d_in[21];  // dec_c_wk
    wp.p[10] = (const float*)d_in[23];  // dec_c_wv
    wp.p[11] = (const float*)d_in[25];  // dec_w1
    wp.p[12] = (const float*)d_in[27];  // dec_w2
    wp.p[13] = (const float*)d_in[29];  // fc_w
    const float* enc_bq = (const float*)d_in[4];
    const float* enc_bk = (const float*)d_in[6];
    const float* enc_bv = (const float*)d_in[8];
    const float* enc_b1 = (const float*)d_in[10];
    const float* enc_b2 = (const float*)d_in[12];
    const float* dec_s_bq = (const float*)d_in[14];
    const float* dec_s_bk = (const float*)d_in[16];
    const float* dec_s_bv = (const float*)d_in[18];
    const float* dec_c_bq = (const float*)d_in[20];
    const float* dec_c_bk = (const float*)d_in[22];
    const float* dec_c_bv = (const float*)d_in[24];
    const float* dec_b1 = (const float*)d_in[26];
    const float* dec_b2 = (const float*)d_in[28];
    const float* fc_b   = (const float*)d_in[30];

    __half *Q1, *Q2, *KVb, *Cq, *Xq, *Yq, *Aq, *Sa, *Pq, *Eq, *Ca, *WALL;
    cudaGetSymbolAddress((void**)&Q1, g_q1);
    cudaGetSymbolAddress((void**)&Q2, g_q2);
    cudaGetSymbolAddress((void**)&KVb, g_kvb);
    cudaGetSymbolAddress((void**)&Cq, g_cq);
    cudaGetSymbolAddress((void**)&Xq, g_xq);
    cudaGetSymbolAddress((void**)&Yq, g_yq);
    cudaGetSymbolAddress((void**)&Aq, g_aq);
    cudaGetSymbolAddress((void**)&Sa, g_sa);
    cudaGetSymbolAddress((void**)&Pq, g_pq);
    cudaGetSymbolAddress((void**)&Eq, g_eq);
    cudaGetSymbolAddress((void**)&Ca, g_ca);
    cudaGetSymbolAddress((void**)&WALL, g_wall);
    float* OUT = (float*)d_out;
    auto WSLOT = [&](int s) { return WALL + ((size_t)s << 20); };

    cudaFuncSetAttribute(gemm_f16<false,false>, cudaFuncAttributeMaxDynamicSharedMemorySize, GEMM_SMEM);
    cudaFuncSetAttribute(gemm_f16<false,true>,  cudaFuncAttributeMaxDynamicSharedMemorySize, GEMM_SMEM);
    cudaFuncSetAttribute(gemm_f16<true,true>,   cudaFuncAttributeMaxDynamicSharedMemorySize, GEMM_SMEM);

    static cudaStream_t s1 = nullptr;
    static cudaEvent_t evFork = nullptr, evJoin = nullptr;
    if (!s1) {
        cudaStreamCreateWithFlags(&s1, cudaStreamNonBlocking);
        cudaEventCreateWithFlags(&evFork, cudaEventDisableTiming);
        cudaEventCreateWithFlags(&evJoin, cudaEventDisableTiming);
    }

    // ---- all weights converted once (serial head, ~15us) ----
    conv_w_all<<<14 * 1024, 256>>>(wp, WALL);
    cudaEventRecord(evFork, 0);
    cudaStreamWaitEvent(s1, evFork, 0);

    const int CA_HALF = MHALF * DDIM / (4 * 256);   // 8192 blocks
    const dim3 GY(8, MHALF / BM);                    // base grid for ng=1

    // run the full network on rows [r, r+MHALF) on stream st
    auto run_half = [&](cudaStream_t st, int r) {
        const size_t rD  = (size_t)r * DDIM;
        const size_t r2D = (size_t)r * 2 * DDIM;
        const size_t r3D = (size_t)r * 3 * DDIM;

        auto g = [&](int ng, const __half* a, int slot,
                     const float* bb0, const float* bb1, const float* bb2,
                     __half* C, int ldc, bool relu) {
            const dim3 grid(ng * 8, MHALF / BM);
            if (relu)
                gemm_f16<true,true><<<grid, 256, GEMM_SMEM, st>>>(
                    a, WSLOT(slot), bb0, bb1, bb2, nullptr, C, ldc);
            else
                gemm_f16<false,true><<<grid, 256, GEMM_SMEM, st>>>(
                    a, WSLOT(slot), bb0, bb1, bb2, nullptr, C, ldc);
        };

        // encoder
        conv_act<true><<<CA_HALF, 256, 0, st>>>(input_seq + rD, pe, Xq + rD);
        g(3, Xq + rD, 0, enc_bq, enc_bk, enc_bv, Q1 + r3D, 3 * DDIM, false);
        attn_kernel<<<MHALF, 128, 0, st>>>(Q1 + r3D, 3 * DDIM, Q1 + r3D + DDIM, 3 * DDIM,
                                           Q1 + r3D + 2 * DDIM, 3 * DDIM, Aq + rD);
        g(1, Aq + rD, 3, enc_b1, enc_b1, enc_b1, Pq + rD, DDIM, true);
        g(1, Pq + rD, 4, enc_b2, enc_b2, enc_b2, Eq + rD, DDIM, false);
        g(2, Eq + rD, 9, dec_c_bk, dec_c_bv, dec_c_bv, KVb + r2D, 2 * DDIM, false);

        // decoder self-attn
        conv_act<false><<<CA_HALF, 256, 0, st>>>(output_seq + rD, nullptr, Yq + rD);
        g(3, Yq + rD, 5, dec_s_bq, dec_s_bk, dec_s_bv, Q2 + r3D, 3 * DDIM, false);
        attn_kernel<<<MHALF, 128, 0, st>>>(Q2 + r3D, 3 * DDIM, Q2 + r3D + DDIM, 3 * DDIM,
                                           Q2 + r3D + 2 * DDIM, 3 * DDIM, Sa + rD);
        g(1, Sa + rD, 8, dec_c_bq, dec_c_bq, dec_c_bq, Cq + rD, DDIM, false);

        // cross-attn + decoder FFN + fc
        attn_kernel<<<MHALF, 128, 0, st>>>(Cq + rD, DDIM, KVb + r2D, 2 * DDIM,
                                           KVb + r2D + DDIM, 2 * DDIM, Ca + rD);
        g(1, Ca + rD, 11, dec_b1, dec_b1, dec_b1, Pq + rD, DDIM, true);
        g(1, Pq + rD, 12, dec_b2, dec_b2, dec_b2, Xq + rD, DDIM, false);
        gemm_f16<false,false><<<GY, 256, GEMM_SMEM, st>>>(
            Xq + rD, WSLOT(13), fc_b, fc_b, fc_b, OUT + rD, nullptr, DDIM);
    };

    run_half(0, 0);           // rows [0, 8192) on default stream
    run_half(s1, MHALF);      // rows [8192, 16384) on s1

    // join: stream 0 waits for s1's half before the graph's end
    cudaEventRecord(evJoin, s1);
    cudaStreamWaitEvent(0, evJoin, 0);
}